// round 15
// baseline (speedup 1.0000x reference)
#include <cuda_runtime.h>
#include <cuda_fp16.h>
#include <cmath>

#define B_   16
#define N_   1024
#define D_   384
#define H_   6
#define DH_  64
#define MTOK (B_ * N_)

// ---------------- scratch (device globals) ----------------
__device__ __half g_wh[1179648];                 // all weights, half
__device__ __half g_t_h[MTOK * D_];              // LN1 out (half)
__device__ __half g_qkv_h[MTOK * 3 * D_];        // q|k|v per token (half)
__device__ __half g_o_h[MTOK * D_];              // attention out (half)
__device__ __half g_x2_h[MTOK * D_];             // LN2 out (half)
__device__ __half g_h_h[MTOK * 2 * D_];          // MLP hidden (half)
__device__ float  g_y[MTOK * D_];                // X + attn (fp32)
__device__ float  g_x2f[MTOK * D_];              // LN2 out (fp32, residual)

#define WOFF_Q  0
#define WOFF_K  147456
#define WOFF_V  294912
#define WOFF_O  442368
#define WOFF_1  589824
#define WOFF_2  884736

#define ONESH 0x3C003C00u     // half2 {1.0, 1.0}

__device__ __forceinline__ float gelu_exact(float x) {
    return 0.5f * x * (1.0f + erff(x * 0.7071067811865475f));
}
__device__ __forceinline__ unsigned scvt(const void* p) {
    return (unsigned)__cvta_generic_to_shared(p);
}
__device__ __forceinline__ unsigned pack2(float a, float b) {
    __half2 h = __floats2half2_rn(a, b);
    return *reinterpret_cast<unsigned*>(&h);
}
__device__ __forceinline__ unsigned ex2_h2(unsigned x) {
    unsigned r;
    asm volatile("ex2.approx.f16x2 %0, %1;" : "=r"(r) : "r"(x));
    return r;
}
__device__ __forceinline__ void mma_f16(float* c, unsigned a0, unsigned a1,
                                        unsigned a2, unsigned a3,
                                        unsigned b0, unsigned b1) {
    asm volatile(
        "mma.sync.aligned.m16n8k16.row.col.f32.f16.f16.f32 "
        "{%0,%1,%2,%3}, {%4,%5,%6,%7}, {%8,%9}, {%0,%1,%2,%3};\n"
        : "+f"(c[0]), "+f"(c[1]), "+f"(c[2]), "+f"(c[3])
        : "r"(a0), "r"(a1), "r"(a2), "r"(a3), "r"(b0), "r"(b1));
}
__device__ __forceinline__ void ldm_x4(unsigned* r, unsigned addr) {
    asm volatile("ldmatrix.sync.aligned.m8n8.x4.shared.b16 {%0,%1,%2,%3}, [%4];"
                 : "=r"(r[0]), "=r"(r[1]), "=r"(r[2]), "=r"(r[3]) : "r"(addr));
}
__device__ __forceinline__ void ldm_x4t(unsigned* r, unsigned addr) {
    asm volatile("ldmatrix.sync.aligned.m8n8.x4.trans.shared.b16 {%0,%1,%2,%3}, [%4];"
                 : "=r"(r[0]), "=r"(r[1]), "=r"(r[2]), "=r"(r[3]) : "r"(addr));
}
__device__ __forceinline__ void cp16(void* s, const void* g) {
    unsigned sa = scvt(s);
    asm volatile("cp.async.ca.shared.global [%0], [%1], 16;" :: "r"(sa), "l"(g));
}

// ---------------- fused prep: weights->half + LN1 (one launch) ----------------
__global__ void prep_k(const float* __restrict__ q, const float* __restrict__ k,
                       const float* __restrict__ v, const float* __restrict__ o,
                       const float* __restrict__ w1, const float* __restrict__ w2,
                       __half* __restrict__ wh,
                       const float* __restrict__ X, const float* __restrict__ ln1w,
                       const float* __restrict__ ln1b, __half* __restrict__ t_h) {
    int bid = blockIdx.x;
    __shared__ float red[4], red2[4];
    if (bid < 9216) {
        int i = bid * 128 + threadIdx.x;
        float val;
        if (i < 147456) val = q[i];
        else if (i < 294912) val = k[i - 147456];
        else if (i < 442368) val = v[i - 294912];
        else if (i < 589824) val = o[i - 442368];
        else if (i < 884736) val = w1[i - 589824];
        else val = w2[i - 884736];
        wh[i] = __float2half(val);
        return;
    }
    int row = bid - 9216;
    const float* xr = X + (size_t)row * D_;
    int tid = threadIdx.x;
    float v0 = xr[tid], v1 = xr[tid + 128], v2 = xr[tid + 256];
    float s = v0 + v1 + v2;
    #pragma unroll
    for (int oo = 16; oo > 0; oo >>= 1) s += __shfl_xor_sync(0xffffffffu, s, oo);
    if ((tid & 31) == 0) red[tid >> 5] = s;
    __syncthreads();
    float mu = (red[0] + red[1] + red[2] + red[3]) * (1.0f / D_);
    float d0 = v0 - mu, d1 = v1 - mu, d2 = v2 - mu;
    float sq = d0 * d0 + d1 * d1 + d2 * d2;
    #pragma unroll
    for (int oo = 16; oo > 0; oo >>= 1) sq += __shfl_xor_sync(0xffffffffu, sq, oo);
    if ((tid & 31) == 0) red2[tid >> 5] = sq;
    __syncthreads();
    float var = (red2[0] + red2[1] + red2[2] + red2[3]) * (1.0f / D_);
    float rstd = rsqrtf(var + 1e-5f);
    __half* oh = t_h + (size_t)row * D_;
    oh[tid]       = __float2half(d0 * rstd * ln1w[tid]       + ln1b[tid]);
    oh[tid + 128] = __float2half(d1 * rstd * ln1w[tid + 128] + ln1b[tid + 128]);
    oh[tid + 256] = __float2half(d2 * rstd * ln1w[tid + 256] + ln1b[tid + 256]);
}

// ---------------- LayerNorm (row D=384) -> half + fp32 ----------------
__global__ void ln_h2(const float* __restrict__ x, const float* __restrict__ w,
                      const float* __restrict__ b, __half* __restrict__ outh,
                      float* __restrict__ outf) {
    int row = blockIdx.x;
    const float* xr = x + (size_t)row * D_;
    int tid = threadIdx.x;
    float v0 = xr[tid], v1 = xr[tid + 128], v2 = xr[tid + 256];
    float s = v0 + v1 + v2;
    __shared__ float red[4], red2[4];
    #pragma unroll
    for (int o = 16; o > 0; o >>= 1) s += __shfl_xor_sync(0xffffffffu, s, o);
    if ((tid & 31) == 0) red[tid >> 5] = s;
    __syncthreads();
    float mu = (red[0] + red[1] + red[2] + red[3]) * (1.0f / D_);
    float d0 = v0 - mu, d1 = v1 - mu, d2 = v2 - mu;
    float sq = d0 * d0 + d1 * d1 + d2 * d2;
    #pragma unroll
    for (int o = 16; o > 0; o >>= 1) sq += __shfl_xor_sync(0xffffffffu, sq, o);
    if ((tid & 31) == 0) red2[tid >> 5] = sq;
    __syncthreads();
    float var = (red2[0] + red2[1] + red2[2] + red2[3]) * (1.0f / D_);
    float rstd = rsqrtf(var + 1e-5f);
    float o0 = d0 * rstd * w[tid]       + b[tid];
    float o1 = d1 * rstd * w[tid + 128] + b[tid + 128];
    float o2 = d2 * rstd * w[tid + 256] + b[tid + 256];
    __half* oh = outh + (size_t)row * D_;
    oh[tid] = __float2half(o0); oh[tid + 128] = __float2half(o1); oh[tid + 256] = __float2half(o2);
    float* of = outf + (size_t)row * D_;
    of[tid] = o0; of[tid + 128] = o1; of[tid + 256] = o2;
}

// ======================= persistent fp16 GEMM, NT, 3-stage cross-tile pipeline ========
// R12 tiling: 256 thr, 8 warps (64x32 warp tiles), BK=32, stride-40 smem, 3-stage ring,
// 1 sync per stage. Grid-stride over output tiles with the cp.async ring continuing
// ACROSS tile boundaries (prologue paid once per CTA; epilogue overlaps prefetch).
#define GST_H  10240                  // halves per stage (A 5120 + W 5120)
#define GST_B  20480                  // bytes per stage

template <int ACT, bool BIAS, bool RES, bool OUTH>
__global__ void __launch_bounds__(256, 2) gemm_p(
    const __half* __restrict__ A,
    const __half* __restrict__ Wa, const __half* __restrict__ Wb2,
    const __half* __restrict__ Wc,
    const float* __restrict__ bias, const float* __restrict__ res,
    __half* __restrict__ Ch, float* __restrict__ Cf,
    int K, int ldc, int nseg, float alpha, int ntn, int ntiles) {
    extern __shared__ __half gsm[];

    int tid = threadIdx.x, lane = tid & 31, wid = tid >> 5;
    int wm = wid & 1, wn = wid >> 1;
    int g = lane >> 2, t = lane & 3;
    int r1 = tid >> 2, c1 = (tid & 3) * 8;
    int soff = r1 * 40 + c1;

    unsigned base = scvt(gsm);
    int arow = lane & 15, asel = (lane & 16) ? 8 : 0;
    int brow = (lane & 7) + ((lane & 16) ? 8 : 0), bsel = (lane & 8) ? 8 : 0;
    unsigned aOff = ((wm * 64 + arow) * 40 + asel) * 2;
    unsigned wOff = 10240 + ((wn * 32 + brow) * 40 + bsel) * 2;

    int nk = K / 32;
    int nMine = (ntiles - blockIdx.x + gridDim.x - 1) / gridDim.x;
    if (nMine <= 0) return;
    int totalS = nMine * nk;

    // prefetch helper: stage ls -> (tile, k), issue 4 cp16 + commit
    auto prefetch = [&](int ls) {
        int i = ls / nk, k = ls - i * nk;
        int ti = blockIdx.x + i * gridDim.x;
        int nI = ti % ntn, mI = ti / ntn;
        int n0g = nI * 128, m0 = mI * 128;
        int seg = n0g / nseg;
        const __half* W = (seg == 0) ? Wa : ((seg == 1) ? Wb2 : Wc);
        int n0 = n0g - seg * nseg;
        const __half* Ap = A + (size_t)(m0 + r1) * K + k * 32 + c1;
        const __half* Wp = W + (size_t)(n0 + r1) * K + k * 32 + c1;
        __half* dA = gsm + (ls % 3) * GST_H + soff;
        __half* dW = dA + 5120;
        cp16(dA, Ap);  cp16(dA + 64 * 40, Ap + (size_t)64 * K);
        cp16(dW, Wp);  cp16(dW + 64 * 40, Wp + (size_t)64 * K);
        asm volatile("cp.async.commit_group;");
    };

    prefetch(0);
    prefetch(1);

    float acc[4][4][4] = {};
    int kk = 0, curTile = 0;

    for (int ls = 0; ls < totalS; ls++) {
        if (ls + 1 < totalS) asm volatile("cp.async.wait_group 1;");
        else                 asm volatile("cp.async.wait_group 0;");
        __syncthreads();

        if (ls + 2 < totalS) prefetch(ls + 2);

        unsigned stB = base + (unsigned)((ls % 3) * GST_B);
        unsigned aBase = stB + aOff, wBase = stB + wOff;
        #pragma unroll
        for (int kc = 0; kc < 2; kc++) {
            unsigned a[4][4];
            #pragma unroll
            for (int mf = 0; mf < 4; mf++)
                ldm_x4(a[mf], aBase + mf * 16 * 80 + kc * 32);
            unsigned b[4][2];
            #pragma unroll
            for (int nfp = 0; nfp < 2; nfp++) {
                unsigned r[4];
                ldm_x4(r, wBase + nfp * 16 * 80 + kc * 32);
                b[2 * nfp][0] = r[0]; b[2 * nfp][1] = r[1];
                b[2 * nfp + 1][0] = r[2]; b[2 * nfp + 1][1] = r[3];
            }
            #pragma unroll
            for (int mf = 0; mf < 4; mf++)
                #pragma unroll
                for (int nf = 0; nf < 4; nf++)
                    mma_f16(acc[mf][nf], a[mf][0], a[mf][1], a[mf][2], a[mf][3],
                            b[nf][0], b[nf][1]);
        }

        if (++kk == nk) {
            kk = 0;
            // ---- epilogue for current tile (overlaps in-flight prefetches) ----
            int ti = blockIdx.x + curTile * gridDim.x;
            curTile++;
            int nI = ti % ntn, mI = ti / ntn;
            int n0g = nI * 128, m0 = mI * 128;
            float asc = ((n0g / nseg) == 0) ? alpha : 1.0f;
            #pragma unroll
            for (int mf = 0; mf < 4; mf++) {
                int r0 = m0 + wm * 64 + mf * 16 + g;
                #pragma unroll
                for (int nf = 0; nf < 4; nf++) {
                    int c = n0g + wn * 32 + nf * 8 + 2 * t;
                    float v0 = acc[mf][nf][0] * asc, v1 = acc[mf][nf][1] * asc;
                    float v2 = acc[mf][nf][2] * asc, v3 = acc[mf][nf][3] * asc;
                    if (BIAS) {
                        float b0v = bias[c], b1v = bias[c + 1];
                        v0 += b0v; v1 += b1v; v2 += b0v; v3 += b1v;
                    }
                    if (ACT == 1) {
                        v0 = gelu_exact(v0); v1 = gelu_exact(v1);
                        v2 = gelu_exact(v2); v3 = gelu_exact(v3);
                    }
                    if (RES) {
                        v0 += res[(size_t)r0 * ldc + c];
                        v1 += res[(size_t)r0 * ldc + c + 1];
                        v2 += res[(size_t)(r0 + 8) * ldc + c];
                        v3 += res[(size_t)(r0 + 8) * ldc + c + 1];
                    }
                    if (OUTH) {
                        *(__half2*)(Ch + (size_t)r0 * ldc + c)       = __floats2half2_rn(v0, v1);
                        *(__half2*)(Ch + (size_t)(r0 + 8) * ldc + c) = __floats2half2_rn(v2, v3);
                    } else {
                        *(float2*)(Cf + (size_t)r0 * ldc + c)       = make_float2(v0, v1);
                        *(float2*)(Cf + (size_t)(r0 + 8) * ldc + c) = make_float2(v2, v3);
                    }
                    acc[mf][nf][0] = acc[mf][nf][1] = acc[mf][nf][2] = acc[mf][nf][3] = 0.f;
                }
            }
        }
    }
}

// ======================= fp16 flash attention (R12 version — best) =======================
#define FQ_STR 72
#define FT 64
#define FKV (FT * FQ_STR)        // 4608 halves per buffer

__global__ void __launch_bounds__(128) flash_h(const __half* __restrict__ qkv,
                                               __half* __restrict__ o_out) {
    extern __shared__ __half fsm[];
    __half* sQ = fsm;                      // 128*72
    __half* sK = fsm + 128 * FQ_STR;       // 2 * FKV
    __half* sV = sK + 2 * FKV;             // 2 * FKV

    int tid = threadIdx.x, lane = tid & 31, wid = tid >> 5;
    int g = lane >> 2, t = lane & 3;
    int bh = blockIdx.y, b = bh / H_, h = bh % H_;
    int q0 = blockIdx.x * 128;
    const __half* qb = qkv + (size_t)b * N_ * 1152 + h * 64;
    const __half* kb = qb + 384;
    const __half* vb = qb + 768;

    #pragma unroll
    for (int i = 0; i < 8; i++) {
        int id = tid + i * 128, row = id >> 3, cg = (id & 7) * 8;
        cp16(&sQ[row * FQ_STR + cg], qb + (size_t)(q0 + row) * 1152 + cg);
    }
    #pragma unroll
    for (int i = 0; i < 4; i++) {
        int id = tid + i * 128, row = id >> 3, cg = (id & 7) * 8;
        cp16(&sK[row * FQ_STR + cg], kb + (size_t)row * 1152 + cg);
        cp16(&sV[row * FQ_STR + cg], vb + (size_t)row * 1152 + cg);
    }
    asm volatile("cp.async.commit_group;");

    unsigned qB = scvt(sQ), kB = scvt(sK), vB = scvt(sV);
    int arow = lane & 15, asel = (lane & 16) ? 8 : 0;
    int brow = (lane & 7) + ((lane & 16) ? 8 : 0), bsel = (lane & 8) ? 8 : 0;
    unsigned kAddr0 = kB + (brow * FQ_STR + bsel) * 2;
    unsigned vAddr0 = vB + (arow * FQ_STR + asel) * 2;

    unsigned qf[2][4][4];
    float lacc[2][4] = {};
    float o[2][8][4] = {};

    for (int j = 0; j < 16; j++) {
        if (j < 15) {
            __half* dK = sK + ((j + 1) & 1) * FKV;
            __half* dV = sV + ((j + 1) & 1) * FKV;
            const __half* kg = kb + (size_t)(j + 1) * FT * 1152;
            const __half* vg = vb + (size_t)(j + 1) * FT * 1152;
            #pragma unroll
            for (int i = 0; i < 4; i++) {
                int id = tid + i * 128, row = id >> 3, cg = (id & 7) * 8;
                cp16(&dK[row * FQ_STR + cg], kg + (size_t)row * 1152 + cg);
                cp16(&dV[row * FQ_STR + cg], vg + (size_t)row * 1152 + cg);
            }
            asm volatile("cp.async.commit_group;");
            asm volatile("cp.async.wait_group 1;");
        } else {
            asm volatile("cp.async.wait_group 0;");
        }
        __syncthreads();

        if (j == 0) {
            #pragma unroll
            for (int grp = 0; grp < 2; grp++) {
                unsigned qAddr = qB + ((32 * wid + 16 * grp + arow) * FQ_STR + asel) * 2;
                #pragma unroll
                for (int kc = 0; kc < 4; kc++)
                    ldm_x4(qf[grp][kc], qAddr + kc * 32);
            }
        }

        unsigned kA = kAddr0 + (j & 1) * (FKV * 2);
        unsigned vA = vAddr0 + (j & 1) * (FKV * 2);

        float sc[2][8][4];
        #pragma unroll
        for (int grp = 0; grp < 2; grp++)
            #pragma unroll
            for (int nf = 0; nf < 8; nf++)
                sc[grp][nf][0] = sc[grp][nf][1] = sc[grp][nf][2] = sc[grp][nf][3] = 0.f;
        #pragma unroll
        for (int kc = 0; kc < 4; kc++) {
            #pragma unroll
            for (int nfp = 0; nfp < 4; nfp++) {
                unsigned bk[4];
                ldm_x4(bk, kA + nfp * 16 * (FQ_STR * 2) + kc * 32);
                #pragma unroll
                for (int grp = 0; grp < 2; grp++) {
                    mma_f16(sc[grp][2 * nfp],     qf[grp][kc][0], qf[grp][kc][1],
                            qf[grp][kc][2], qf[grp][kc][3], bk[0], bk[1]);
                    mma_f16(sc[grp][2 * nfp + 1], qf[grp][kc][0], qf[grp][kc][1],
                            qf[grp][kc][2], qf[grp][kc][3], bk[2], bk[3]);
                }
            }
        }

        unsigned ph[2][8][2];
        #pragma unroll
        for (int grp = 0; grp < 2; grp++) {
            #pragma unroll
            for (int nf = 0; nf < 8; nf++) {
                ph[grp][nf][0] = ex2_h2(pack2(sc[grp][nf][0], sc[grp][nf][1]));
                ph[grp][nf][1] = ex2_h2(pack2(sc[grp][nf][2], sc[grp][nf][3]));
            }
        }

        #pragma unroll
        for (int kc2 = 0; kc2 < 4; kc2++)
            #pragma unroll
            for (int grp = 0; grp < 2; grp++)
                mma_f16(lacc[grp], ph[grp][2 * kc2][0], ph[grp][2 * kc2][1],
                        ph[grp][2 * kc2 + 1][0], ph[grp][2 * kc2 + 1][1],
                        ONESH, ONESH);

        #pragma unroll
        for (int kc2 = 0; kc2 < 4; kc2++) {
            #pragma unroll
            for (int nfq = 0; nfq < 4; nfq++) {
                unsigned bv[4];
                ldm_x4t(bv, vA + kc2 * 16 * (FQ_STR * 2) + nfq * 32);
                #pragma unroll
                for (int grp = 0; grp < 2; grp++) {
                    unsigned a0 = ph[grp][2 * kc2][0], a1 = ph[grp][2 * kc2][1];
                    unsigned a2 = ph[grp][2 * kc2 + 1][0], a3 = ph[grp][2 * kc2 + 1][1];
                    mma_f16(o[grp][2 * nfq],     a0, a1, a2, a3, bv[0], bv[1]);
                    mma_f16(o[grp][2 * nfq + 1], a0, a1, a2, a3, bv[2], bv[3]);
                }
            }
        }
        __syncthreads();
    }

    #pragma unroll
    for (int grp = 0; grp < 2; grp++) {
        float i0 = 1.0f / lacc[grp][0], i1 = 1.0f / lacc[grp][2];
        size_t tok0 = (size_t)(b * N_ + q0 + 32 * wid + 16 * grp + g);
        __half* out0 = o_out + tok0 * D_ + h * 64;
        __half* out1 = out0 + (size_t)8 * D_;
        #pragma unroll
        for (int nf2 = 0; nf2 < 8; nf2++) {
            int c = nf2 * 8 + 2 * t;
            *(__half2*)(out0 + c) = __floats2half2_rn(o[grp][nf2][0] * i0, o[grp][nf2][1] * i0);
            *(__half2*)(out1 + c) = __floats2half2_rn(o[grp][nf2][2] * i1, o[grp][nf2][3] * i1);
        }
    }
}

// ---------------- launch ----------------
static inline int balanced_blocks(int ntiles) {
    int w = (ntiles + 295) / 296;
    return (ntiles + w - 1) / w;
}

extern "C" void kernel_launch(void* const* d_in, const int* in_sizes, int n_in,
                              void* d_out, int out_size) {
    const float* X    = (const float*)d_in[0];
    const float* Wq   = (const float*)d_in[1];
    const float* Wk   = (const float*)d_in[2];
    const float* Wv   = (const float*)d_in[3];
    const float* Wo   = (const float*)d_in[4];
    const float* bo   = (const float*)d_in[5];
    const float* ln1w = (const float*)d_in[6];
    const float* ln1b = (const float*)d_in[7];
    const float* ln2w = (const float*)d_in[8];
    const float* ln2b = (const float*)d_in[9];
    const float* W1   = (const float*)d_in[10];
    const float* b1   = (const float*)d_in[11];
    const float* W2   = (const float*)d_in[12];
    const float* b2   = (const float*)d_in[13];
    float* out = (float*)d_out;

    __half *wh, *t_h, *qkv_h, *o_h, *x2_h, *h_h;
    float *y, *x2f;
    cudaGetSymbolAddress((void**)&wh,    g_wh);
    cudaGetSymbolAddress((void**)&t_h,   g_t_h);
    cudaGetSymbolAddress((void**)&qkv_h, g_qkv_h);
    cudaGetSymbolAddress((void**)&o_h,   g_o_h);
    cudaGetSymbolAddress((void**)&x2_h,  g_x2_h);
    cudaGetSymbolAddress((void**)&h_h,   g_h_h);
    cudaGetSymbolAddress((void**)&y,     g_y);
    cudaGetSymbolAddress((void**)&x2f,   g_x2f);

    const int gsmem = 3 * GST_B;                        // 61440 B
    const int fa_smem = (128 * FQ_STR + 4 * FKV) * 2;   // 55296 B
    cudaFuncSetAttribute(flash_h, cudaFuncAttributeMaxDynamicSharedMemorySize, fa_smem);
    cudaFuncSetAttribute(gemm_p<0, false, false, true>,
                         cudaFuncAttributeMaxDynamicSharedMemorySize, gsmem);
    cudaFuncSetAttribute(gemm_p<0, true, true, false>,
                         cudaFuncAttributeMaxDynamicSharedMemorySize, gsmem);
    cudaFuncSetAttribute(gemm_p<1, true, false, true>,
                         cudaFuncAttributeMaxDynamicSharedMemorySize, gsmem);

    const float qscale = 0.125f * 1.4426950408889634f;   // 1/sqrt(64) * log2(e)

    // 0) weights->half + LN1 (single launch)
    prep_k<<<9216 + MTOK, 128>>>(Wq, Wk, Wv, Wo, W1, W2, wh, X, ln1w, ln1b, t_h);

    // 1) fused QKV projection (persistent); Q segment pre-scaled to log2 domain
    {
        int ntiles = 9 * 128;
        gemm_p<0, false, false, true><<<balanced_blocks(ntiles), 256, gsmem>>>(t_h,
            wh + WOFF_Q, wh + WOFF_K, wh + WOFF_V,
            nullptr, nullptr, qkv_h, nullptr, D_, 3 * D_, 384, qscale, 9, ntiles);
    }

    // 2) flash attention -> o_h
    {
        dim3 gsz(8, B_ * H_);
        flash_h<<<gsz, 128, fa_smem>>>(qkv_h, o_h);
    }

    // 3) y = X + (o @ Wo^T + bo)   (fp32 out)
    {
        int ntiles = 3 * 128;
        gemm_p<0, true, true, false><<<balanced_blocks(ntiles), 256, gsmem>>>(o_h,
            wh + WOFF_O, wh + WOFF_O, wh + WOFF_O,
            bo, X, nullptr, y, D_, D_, 1 << 30, 1.0f, 3, ntiles);
    }

    // 4) LN2 -> half + fp32
    ln_h2<<<MTOK, 128>>>(y, ln2w, ln2b, x2_h, x2f);

    // 5) h = gelu(x2 @ W1^T + b1) -> half
    {
        int ntiles = 6 * 128;
        gemm_p<1, true, false, true><<<balanced_blocks(ntiles), 256, gsmem>>>(x2_h,
            wh + WOFF_1, wh + WOFF_1, wh + WOFF_1,
            b1, nullptr, h_h, nullptr, D_, 2 * D_, 1 << 30, 1.0f, 6, ntiles);
    }

    // 6) out = x2f + (h @ W2^T + b2)   (fp32 out)
    {
        int ntiles = 3 * 128;
        gemm_p<0, true, true, false><<<balanced_blocks(ntiles), 256, gsmem>>>(h_h,
            wh + WOFF_2, wh + WOFF_2, wh + WOFF_2,
            b2, x2f, nullptr, out, 2 * D_, D_, 1 << 30, 1.0f, 3, ntiles);
    }
}

// round 16
// speedup vs baseline: 1.1140x; 1.1140x over previous
#include <cuda_runtime.h>
#include <cuda_fp16.h>
#include <cmath>

#define B_   16
#define N_   1024
#define D_   384
#define H_   6
#define DH_  64
#define MTOK (B_ * N_)

// ---------------- scratch (device globals) ----------------
__device__ __half g_wh[1179648];                 // all weights, half
__device__ __half g_t_h[MTOK * D_];              // LN1 out (half)
__device__ __half g_qkv_h[MTOK * 3 * D_];        // q|k|v per token (half)
__device__ __half g_o_h[MTOK * D_];              // attention out (half)
__device__ __half g_x2_h[MTOK * D_];             // LN2 out (half)
__device__ __half g_h_h[MTOK * 2 * D_];          // MLP hidden (half)
__device__ float  g_y[MTOK * D_];                // X + attn (fp32)
__device__ float  g_x2f[MTOK * D_];              // LN2 out (fp32, residual)

#define WOFF_Q  0
#define WOFF_K  147456
#define WOFF_V  294912
#define WOFF_O  442368
#define WOFF_1  589824
#define WOFF_2  884736

#define ONESH 0x3C003C00u     // half2 {1.0, 1.0}

__device__ __forceinline__ float gelu_exact(float x) {
    return 0.5f * x * (1.0f + erff(x * 0.7071067811865475f));
}
__device__ __forceinline__ unsigned scvt(const void* p) {
    return (unsigned)__cvta_generic_to_shared(p);
}
__device__ __forceinline__ unsigned pack2(float a, float b) {
    __half2 h = __floats2half2_rn(a, b);
    return *reinterpret_cast<unsigned*>(&h);
}
__device__ __forceinline__ unsigned ex2_h2(unsigned x) {
    unsigned r;
    asm volatile("ex2.approx.f16x2 %0, %1;" : "=r"(r) : "r"(x));
    return r;
}
__device__ __forceinline__ void mma_f16(float* c, unsigned a0, unsigned a1,
                                        unsigned a2, unsigned a3,
                                        unsigned b0, unsigned b1) {
    asm volatile(
        "mma.sync.aligned.m16n8k16.row.col.f32.f16.f16.f32 "
        "{%0,%1,%2,%3}, {%4,%5,%6,%7}, {%8,%9}, {%0,%1,%2,%3};\n"
        : "+f"(c[0]), "+f"(c[1]), "+f"(c[2]), "+f"(c[3])
        : "r"(a0), "r"(a1), "r"(a2), "r"(a3), "r"(b0), "r"(b1));
}
__device__ __forceinline__ void ldm_x4(unsigned* r, unsigned addr) {
    asm volatile("ldmatrix.sync.aligned.m8n8.x4.shared.b16 {%0,%1,%2,%3}, [%4];"
                 : "=r"(r[0]), "=r"(r[1]), "=r"(r[2]), "=r"(r[3]) : "r"(addr));
}
__device__ __forceinline__ void ldm_x4t(unsigned* r, unsigned addr) {
    asm volatile("ldmatrix.sync.aligned.m8n8.x4.trans.shared.b16 {%0,%1,%2,%3}, [%4];"
                 : "=r"(r[0]), "=r"(r[1]), "=r"(r[2]), "=r"(r[3]) : "r"(addr));
}
__device__ __forceinline__ void cp16(void* s, const void* g) {
    unsigned sa = scvt(s);
    asm volatile("cp.async.ca.shared.global [%0], [%1], 16;" :: "r"(sa), "l"(g));
}

// ---------------- fused prep: weights->half + LN1 (one launch) ----------------
__global__ void prep_k(const float* __restrict__ q, const float* __restrict__ k,
                       const float* __restrict__ v, const float* __restrict__ o,
                       const float* __restrict__ w1, const float* __restrict__ w2,
                       __half* __restrict__ wh,
                       const float* __restrict__ X, const float* __restrict__ ln1w,
                       const float* __restrict__ ln1b, __half* __restrict__ t_h) {
    int bid = blockIdx.x;
    __shared__ float red[4], red2[4];
    if (bid < 9216) {
        int i = bid * 128 + threadIdx.x;
        float val;
        if (i < 147456) val = q[i];
        else if (i < 294912) val = k[i - 147456];
        else if (i < 442368) val = v[i - 294912];
        else if (i < 589824) val = o[i - 442368];
        else if (i < 884736) val = w1[i - 589824];
        else val = w2[i - 884736];
        wh[i] = __float2half(val);
        return;
    }
    int row = bid - 9216;
    const float* xr = X + (size_t)row * D_;
    int tid = threadIdx.x;
    float v0 = xr[tid], v1 = xr[tid + 128], v2 = xr[tid + 256];
    float s = v0 + v1 + v2;
    #pragma unroll
    for (int oo = 16; oo > 0; oo >>= 1) s += __shfl_xor_sync(0xffffffffu, s, oo);
    if ((tid & 31) == 0) red[tid >> 5] = s;
    __syncthreads();
    float mu = (red[0] + red[1] + red[2] + red[3]) * (1.0f / D_);
    float d0 = v0 - mu, d1 = v1 - mu, d2 = v2 - mu;
    float sq = d0 * d0 + d1 * d1 + d2 * d2;
    #pragma unroll
    for (int oo = 16; oo > 0; oo >>= 1) sq += __shfl_xor_sync(0xffffffffu, sq, oo);
    if ((tid & 31) == 0) red2[tid >> 5] = sq;
    __syncthreads();
    float var = (red2[0] + red2[1] + red2[2] + red2[3]) * (1.0f / D_);
    float rstd = rsqrtf(var + 1e-5f);
    __half* oh = t_h + (size_t)row * D_;
    oh[tid]       = __float2half(d0 * rstd * ln1w[tid]       + ln1b[tid]);
    oh[tid + 128] = __float2half(d1 * rstd * ln1w[tid + 128] + ln1b[tid + 128]);
    oh[tid + 256] = __float2half(d2 * rstd * ln1w[tid + 256] + ln1b[tid + 256]);
}

// ---------------- LayerNorm (row D=384) -> half + fp32 ----------------
__global__ void ln_h2(const float* __restrict__ x, const float* __restrict__ w,
                      const float* __restrict__ b, __half* __restrict__ outh,
                      float* __restrict__ outf) {
    int row = blockIdx.x;
    const float* xr = x + (size_t)row * D_;
    int tid = threadIdx.x;
    float v0 = xr[tid], v1 = xr[tid + 128], v2 = xr[tid + 256];
    float s = v0 + v1 + v2;
    __shared__ float red[4], red2[4];
    #pragma unroll
    for (int o = 16; o > 0; o >>= 1) s += __shfl_xor_sync(0xffffffffu, s, o);
    if ((tid & 31) == 0) red[tid >> 5] = s;
    __syncthreads();
    float mu = (red[0] + red[1] + red[2] + red[3]) * (1.0f / D_);
    float d0 = v0 - mu, d1 = v1 - mu, d2 = v2 - mu;
    float sq = d0 * d0 + d1 * d1 + d2 * d2;
    #pragma unroll
    for (int o = 16; o > 0; o >>= 1) sq += __shfl_xor_sync(0xffffffffu, sq, o);
    if ((tid & 31) == 0) red2[tid >> 5] = sq;
    __syncthreads();
    float var = (red2[0] + red2[1] + red2[2] + red2[3]) * (1.0f / D_);
    float rstd = rsqrtf(var + 1e-5f);
    float o0 = d0 * rstd * w[tid]       + b[tid];
    float o1 = d1 * rstd * w[tid + 128] + b[tid + 128];
    float o2 = d2 * rstd * w[tid + 256] + b[tid + 256];
    __half* oh = outh + (size_t)row * D_;
    oh[tid] = __float2half(o0); oh[tid + 128] = __float2half(o1); oh[tid + 256] = __float2half(o2);
    float* of = outf + (size_t)row * D_;
    of[tid] = o0; of[tid + 128] = o1; of[tid + 256] = o2;
}

// ======================= fp16 tensor-core GEMM, NT, 3-stage 1-sync (R12) ==============
#define GST_H  10240                  // halves per stage (A 5120 + W 5120)
#define GST_B  20480                  // bytes per stage

template <int ACT, bool BIAS, bool RES, bool OUTH>
__global__ void __launch_bounds__(256) gemm_h(
    const __half* __restrict__ A,
    const __half* __restrict__ Wa, const __half* __restrict__ Wb2,
    const __half* __restrict__ Wc,
    const float* __restrict__ bias, const float* __restrict__ res,
    __half* __restrict__ Ch, float* __restrict__ Cf,
    int K, int ldc, int nseg, float alpha) {
    extern __shared__ __half gsm[];

    int tid = threadIdx.x, lane = tid & 31, wid = tid >> 5;
    int wm = wid & 1, wn = wid >> 1;
    int g = lane >> 2, t = lane & 3;
    int m0 = blockIdx.y * 128, n0g = blockIdx.x * 128;
    int seg = n0g / nseg;
    const __half* W = (seg == 0) ? Wa : ((seg == 1) ? Wb2 : Wc);
    int n0 = n0g - seg * nseg;
    float asc = (seg == 0) ? alpha : 1.0f;

    int r1 = tid >> 2, c1 = (tid & 3) * 8;      // row, col(halves)
    const __half* Ap = A + (size_t)(m0 + r1) * K + c1;
    const __half* Wp = W + (size_t)(n0 + r1) * K + c1;

    unsigned base = scvt(gsm);
    int arow = lane & 15, asel = (lane & 16) ? 8 : 0;
    int brow = (lane & 7) + ((lane & 16) ? 8 : 0), bsel = (lane & 8) ? 8 : 0;
    unsigned aOff = ((wm * 64 + arow) * 40 + asel) * 2;
    unsigned wOff = 10240 + ((wn * 32 + brow) * 40 + bsel) * 2;

    float acc[4][4][4] = {};
    int nk = K / 32;

    #pragma unroll
    for (int s = 0; s < 2; s++) {
        __half* dA = gsm + s * GST_H + r1 * 40 + c1;
        __half* dW = dA + 5120;
        cp16(dA, Ap + s * 32);           cp16(dA + 64 * 40, Ap + (size_t)64 * K + s * 32);
        cp16(dW, Wp + s * 32);           cp16(dW + 64 * 40, Wp + (size_t)64 * K + s * 32);
        asm volatile("cp.async.commit_group;");
    }

    for (int it = 0; it < nk; it++) {
        if (it + 1 < nk) asm volatile("cp.async.wait_group 1;");
        else             asm volatile("cp.async.wait_group 0;");
        __syncthreads();

        if (it + 2 < nk) {
            int st = (it + 2) % 3;
            int k0 = (it + 2) * 32;
            __half* dA = gsm + st * GST_H + r1 * 40 + c1;
            __half* dW = dA + 5120;
            cp16(dA, Ap + k0);           cp16(dA + 64 * 40, Ap + (size_t)64 * K + k0);
            cp16(dW, Wp + k0);           cp16(dW + 64 * 40, Wp + (size_t)64 * K + k0);
            asm volatile("cp.async.commit_group;");
        }

        unsigned stB = base + (unsigned)((it % 3) * GST_B);
        unsigned aBase = stB + aOff, wBase = stB + wOff;
        #pragma unroll
        for (int kc = 0; kc < 2; kc++) {
            unsigned a[4][4];
            #pragma unroll
            for (int mf = 0; mf < 4; mf++)
                ldm_x4(a[mf], aBase + mf * 16 * 80 + kc * 32);
            unsigned b[4][2];
            #pragma unroll
            for (int nfp = 0; nfp < 2; nfp++) {
                unsigned r[4];
                ldm_x4(r, wBase + nfp * 16 * 80 + kc * 32);
                b[2 * nfp][0] = r[0]; b[2 * nfp][1] = r[1];
                b[2 * nfp + 1][0] = r[2]; b[2 * nfp + 1][1] = r[3];
            }
            #pragma unroll
            for (int mf = 0; mf < 4; mf++)
                #pragma unroll
                for (int nf = 0; nf < 4; nf++)
                    mma_f16(acc[mf][nf], a[mf][0], a[mf][1], a[mf][2], a[mf][3],
                            b[nf][0], b[nf][1]);
        }
    }

    #pragma unroll
    for (int mf = 0; mf < 4; mf++) {
        int r0 = m0 + wm * 64 + mf * 16 + g;
        #pragma unroll
        for (int nf = 0; nf < 4; nf++) {
            int c = n0g + wn * 32 + nf * 8 + 2 * t;
            float v0 = acc[mf][nf][0] * asc, v1 = acc[mf][nf][1] * asc;
            float v2 = acc[mf][nf][2] * asc, v3 = acc[mf][nf][3] * asc;
            if (BIAS) {
                float b0v = bias[c], b1v = bias[c + 1];
                v0 += b0v; v1 += b1v; v2 += b0v; v3 += b1v;
            }
            if (ACT == 1) {
                v0 = gelu_exact(v0); v1 = gelu_exact(v1);
                v2 = gelu_exact(v2); v3 = gelu_exact(v3);
            }
            if (RES) {
                v0 += res[(size_t)r0 * ldc + c];
                v1 += res[(size_t)r0 * ldc + c + 1];
                v2 += res[(size_t)(r0 + 8) * ldc + c];
                v3 += res[(size_t)(r0 + 8) * ldc + c + 1];
            }
            if (OUTH) {
                *(__half2*)(Ch + (size_t)r0 * ldc + c)       = __floats2half2_rn(v0, v1);
                *(__half2*)(Ch + (size_t)(r0 + 8) * ldc + c) = __floats2half2_rn(v2, v3);
            } else {
                *(float2*)(Cf + (size_t)r0 * ldc + c)       = make_float2(v0, v1);
                *(float2*)(Cf + (size_t)(r0 + 8) * ldc + c) = make_float2(v2, v3);
            }
        }
    }
}

// ======================= fp16 flash attention (R12 version — best) =======================
#define FQ_STR 72
#define FT 64
#define FKV (FT * FQ_STR)        // 4608 halves per buffer

__global__ void __launch_bounds__(128) flash_h(const __half* __restrict__ qkv,
                                               __half* __restrict__ o_out) {
    extern __shared__ __half fsm[];
    __half* sQ = fsm;                      // 128*72
    __half* sK = fsm + 128 * FQ_STR;       // 2 * FKV
    __half* sV = sK + 2 * FKV;             // 2 * FKV

    int tid = threadIdx.x, lane = tid & 31, wid = tid >> 5;
    int g = lane >> 2, t = lane & 3;
    int bh = blockIdx.y, b = bh / H_, h = bh % H_;
    int q0 = blockIdx.x * 128;
    const __half* qb = qkv + (size_t)b * N_ * 1152 + h * 64;
    const __half* kb = qb + 384;
    const __half* vb = qb + 768;

    #pragma unroll
    for (int i = 0; i < 8; i++) {
        int id = tid + i * 128, row = id >> 3, cg = (id & 7) * 8;
        cp16(&sQ[row * FQ_STR + cg], qb + (size_t)(q0 + row) * 1152 + cg);
    }
    #pragma unroll
    for (int i = 0; i < 4; i++) {
        int id = tid + i * 128, row = id >> 3, cg = (id & 7) * 8;
        cp16(&sK[row * FQ_STR + cg], kb + (size_t)row * 1152 + cg);
        cp16(&sV[row * FQ_STR + cg], vb + (size_t)row * 1152 + cg);
    }
    asm volatile("cp.async.commit_group;");

    unsigned qB = scvt(sQ), kB = scvt(sK), vB = scvt(sV);
    int arow = lane & 15, asel = (lane & 16) ? 8 : 0;
    int brow = (lane & 7) + ((lane & 16) ? 8 : 0), bsel = (lane & 8) ? 8 : 0;
    unsigned kAddr0 = kB + (brow * FQ_STR + bsel) * 2;
    unsigned vAddr0 = vB + (arow * FQ_STR + asel) * 2;

    unsigned qf[2][4][4];
    float lacc[2][4] = {};
    float o[2][8][4] = {};

    for (int j = 0; j < 16; j++) {
        if (j < 15) {
            __half* dK = sK + ((j + 1) & 1) * FKV;
            __half* dV = sV + ((j + 1) & 1) * FKV;
            const __half* kg = kb + (size_t)(j + 1) * FT * 1152;
            const __half* vg = vb + (size_t)(j + 1) * FT * 1152;
            #pragma unroll
            for (int i = 0; i < 4; i++) {
                int id = tid + i * 128, row = id >> 3, cg = (id & 7) * 8;
                cp16(&dK[row * FQ_STR + cg], kg + (size_t)row * 1152 + cg);
                cp16(&dV[row * FQ_STR + cg], vg + (size_t)row * 1152 + cg);
            }
            asm volatile("cp.async.commit_group;");
            asm volatile("cp.async.wait_group 1;");
        } else {
            asm volatile("cp.async.wait_group 0;");
        }
        __syncthreads();

        if (j == 0) {
            #pragma unroll
            for (int grp = 0; grp < 2; grp++) {
                unsigned qAddr = qB + ((32 * wid + 16 * grp + arow) * FQ_STR + asel) * 2;
                #pragma unroll
                for (int kc = 0; kc < 4; kc++)
                    ldm_x4(qf[grp][kc], qAddr + kc * 32);
            }
        }

        unsigned kA = kAddr0 + (j & 1) * (FKV * 2);
        unsigned vA = vAddr0 + (j & 1) * (FKV * 2);

        // ---- S = Q' K^T (Q pre-scaled to log2 domain) ----
        float sc[2][8][4];
        #pragma unroll
        for (int grp = 0; grp < 2; grp++)
            #pragma unroll
            for (int nf = 0; nf < 8; nf++)
                sc[grp][nf][0] = sc[grp][nf][1] = sc[grp][nf][2] = sc[grp][nf][3] = 0.f;
        #pragma unroll
        for (int kc = 0; kc < 4; kc++) {
            #pragma unroll
            for (int nfp = 0; nfp < 4; nfp++) {
                unsigned bk[4];
                ldm_x4(bk, kA + nfp * 16 * (FQ_STR * 2) + kc * 32);
                #pragma unroll
                for (int grp = 0; grp < 2; grp++) {
                    mma_f16(sc[grp][2 * nfp],     qf[grp][kc][0], qf[grp][kc][1],
                            qf[grp][kc][2], qf[grp][kc][3], bk[0], bk[1]);
                    mma_f16(sc[grp][2 * nfp + 1], qf[grp][kc][0], qf[grp][kc][1],
                            qf[grp][kc][2], qf[grp][kc][3], bk[2], bk[3]);
                }
            }
        }

        // ---- P = 2^S via ex2.approx.f16x2 ----
        unsigned ph[2][8][2];
        #pragma unroll
        for (int grp = 0; grp < 2; grp++) {
            #pragma unroll
            for (int nf = 0; nf < 8; nf++) {
                ph[grp][nf][0] = ex2_h2(pack2(sc[grp][nf][0], sc[grp][nf][1]));
                ph[grp][nf][1] = ex2_h2(pack2(sc[grp][nf][2], sc[grp][nf][3]));
            }
        }

        // ---- l += P @ ones ----
        #pragma unroll
        for (int kc2 = 0; kc2 < 4; kc2++)
            #pragma unroll
            for (int grp = 0; grp < 2; grp++)
                mma_f16(lacc[grp], ph[grp][2 * kc2][0], ph[grp][2 * kc2][1],
                        ph[grp][2 * kc2 + 1][0], ph[grp][2 * kc2 + 1][1],
                        ONESH, ONESH);

        // ---- O += P V ----
        #pragma unroll
        for (int kc2 = 0; kc2 < 4; kc2++) {
            #pragma unroll
            for (int nfq = 0; nfq < 4; nfq++) {
                unsigned bv[4];
                ldm_x4t(bv, vA + kc2 * 16 * (FQ_STR * 2) + nfq * 32);
                #pragma unroll
                for (int grp = 0; grp < 2; grp++) {
                    unsigned a0 = ph[grp][2 * kc2][0], a1 = ph[grp][2 * kc2][1];
                    unsigned a2 = ph[grp][2 * kc2 + 1][0], a3 = ph[grp][2 * kc2 + 1][1];
                    mma_f16(o[grp][2 * nfq],     a0, a1, a2, a3, bv[0], bv[1]);
                    mma_f16(o[grp][2 * nfq + 1], a0, a1, a2, a3, bv[2], bv[3]);
                }
            }
        }
        __syncthreads();
    }

    // ---- epilogue: l already reduced by the ones-MMA ----
    #pragma unroll
    for (int grp = 0; grp < 2; grp++) {
        float i0 = 1.0f / lacc[grp][0], i1 = 1.0f / lacc[grp][2];
        size_t tok0 = (size_t)(b * N_ + q0 + 32 * wid + 16 * grp + g);
        __half* out0 = o_out + tok0 * D_ + h * 64;
        __half* out1 = out0 + (size_t)8 * D_;
        #pragma unroll
        for (int nf2 = 0; nf2 < 8; nf2++) {
            int c = nf2 * 8 + 2 * t;
            *(__half2*)(out0 + c) = __floats2half2_rn(o[grp][nf2][0] * i0, o[grp][nf2][1] * i0);
            *(__half2*)(out1 + c) = __floats2half2_rn(o[grp][nf2][2] * i1, o[grp][nf2][3] * i1);
        }
    }
}

// ---------------- launch ----------------
extern "C" void kernel_launch(void* const* d_in, const int* in_sizes, int n_in,
                              void* d_out, int out_size) {
    const float* X    = (const float*)d_in[0];
    const float* Wq   = (const float*)d_in[1];
    const float* Wk   = (const float*)d_in[2];
    const float* Wv   = (const float*)d_in[3];
    const float* Wo   = (const float*)d_in[4];
    const float* bo   = (const float*)d_in[5];
    const float* ln1w = (const float*)d_in[6];
    const float* ln1b = (const float*)d_in[7];
    const float* ln2w = (const float*)d_in[8];
    const float* ln2b = (const float*)d_in[9];
    const float* W1   = (const float*)d_in[10];
    const float* b1   = (const float*)d_in[11];
    const float* W2   = (const float*)d_in[12];
    const float* b2   = (const float*)d_in[13];
    float* out = (float*)d_out;

    __half *wh, *t_h, *qkv_h, *o_h, *x2_h, *h_h;
    float *y, *x2f;
    cudaGetSymbolAddress((void**)&wh,    g_wh);
    cudaGetSymbolAddress((void**)&t_h,   g_t_h);
    cudaGetSymbolAddress((void**)&qkv_h, g_qkv_h);
    cudaGetSymbolAddress((void**)&o_h,   g_o_h);
    cudaGetSymbolAddress((void**)&x2_h,  g_x2_h);
    cudaGetSymbolAddress((void**)&h_h,   g_h_h);
    cudaGetSymbolAddress((void**)&y,     g_y);
    cudaGetSymbolAddress((void**)&x2f,   g_x2f);

    const int gsmem = 3 * GST_B;                        // 61440 B
    const int fa_smem = (128 * FQ_STR + 4 * FKV) * 2;   // 55296 B
    cudaFuncSetAttribute(flash_h, cudaFuncAttributeMaxDynamicSharedMemorySize, fa_smem);
    cudaFuncSetAttribute(gemm_h<0, false, false, true>,
                         cudaFuncAttributeMaxDynamicSharedMemorySize, gsmem);
    cudaFuncSetAttribute(gemm_h<0, true, true, false>,
                         cudaFuncAttributeMaxDynamicSharedMemorySize, gsmem);
    cudaFuncSetAttribute(gemm_h<1, true, false, true>,
                         cudaFuncAttributeMaxDynamicSharedMemorySize, gsmem);

    const float qscale = 0.125f * 1.4426950408889634f;   // 1/sqrt(64) * log2(e)

    // 0) weights->half + LN1 (single launch)
    prep_k<<<9216 + MTOK, 128>>>(Wq, Wk, Wv, Wo, W1, W2, wh, X, ln1w, ln1b, t_h);

    // 1) fused QKV projection; Q segment pre-scaled to log2 domain
    {
        dim3 gsz(9, 128);
        gemm_h<0, false, false, true><<<gsz, 256, gsmem>>>(t_h,
            wh + WOFF_Q, wh + WOFF_K, wh + WOFF_V,
            nullptr, nullptr, qkv_h, nullptr, D_, 3 * D_, 384, qscale);
    }

    // 2) flash attention -> o_h
    {
        dim3 gsz(8, B_ * H_);
        flash_h<<<gsz, 128, fa_smem>>>(qkv_h, o_h);
    }

    // 3) y = X + (o @ Wo^T + bo)   (fp32 out)
    {
        dim3 gsz(3, 128);
        gemm_h<0, true, true, false><<<gsz, 256, gsmem>>>(o_h,
            wh + WOFF_O, wh + WOFF_O, wh + WOFF_O,
            bo, X, nullptr, y, D_, D_, 1 << 30, 1.0f);
    }

    // 4) LN2 -> half + fp32
    ln_h2<<<MTOK, 128>>>(y, ln2w, ln2b, x2_h, x2f);

    // 5) h = gelu(x2 @ W1^T + b1) -> half
    {
        dim3 gsz(6, 128);
        gemm_h<1, true, false, true><<<gsz, 256, gsmem>>>(x2_h,
            wh + WOFF_1, wh + WOFF_1, wh + WOFF_1,
            b1, nullptr, h_h, nullptr, D_, 2 * D_, 1 << 30, 1.0f);
    }

    // 6) out = x2f + (h @ W2^T + b2)   (fp32 out)
    {
        dim3 gsz(3, 128);
        gemm_h<0, true, true, false><<<gsz, 256, gsmem>>>(h_h,
            wh + WOFF_2, wh + WOFF_2, wh + WOFF_2,
            b2, x2f, nullptr, out, 2 * D_, D_, 1 << 30, 1.0f);
    }
}

// round 17
// speedup vs baseline: 1.1501x; 1.0325x over previous
#include <cuda_runtime.h>
#include <cuda_fp16.h>
#include <cmath>

#define B_   16
#define N_   1024
#define D_   384
#define H_   6
#define DH_  64
#define MTOK (B_ * N_)

// ---------------- scratch (device globals) ----------------
__device__ __half g_wh[1179648];                 // all weights, half
__device__ __half g_t_h[MTOK * D_];              // LN1 out (half)
__device__ __half g_qkv_h[MTOK * 3 * D_];        // q|k|v per token (half)
__device__ __half g_o_h[MTOK * D_];              // attention out (half)
__device__ __half g_x2_h[MTOK * D_];             // LN2 out (half)
__device__ __half g_h_h[MTOK * 2 * D_];          // MLP hidden (half)
__device__ float  g_y[MTOK * D_];                // X + attn (fp32)

#define WOFF_Q  0
#define WOFF_K  147456
#define WOFF_V  294912
#define WOFF_O  442368
#define WOFF_1  589824
#define WOFF_2  884736

#define ONESH 0x3C003C00u     // half2 {1.0, 1.0}

__device__ __forceinline__ float gelu_exact(float x) {
    return 0.5f * x * (1.0f + erff(x * 0.7071067811865475f));
}
__device__ __forceinline__ unsigned scvt(const void* p) {
    return (unsigned)__cvta_generic_to_shared(p);
}
__device__ __forceinline__ unsigned pack2(float a, float b) {
    __half2 h = __floats2half2_rn(a, b);
    return *reinterpret_cast<unsigned*>(&h);
}
__device__ __forceinline__ unsigned ex2_h2(unsigned x) {
    unsigned r;
    asm volatile("ex2.approx.f16x2 %0, %1;" : "=r"(r) : "r"(x));
    return r;
}
__device__ __forceinline__ void mma_f16(float* c, unsigned a0, unsigned a1,
                                        unsigned a2, unsigned a3,
                                        unsigned b0, unsigned b1) {
    asm volatile(
        "mma.sync.aligned.m16n8k16.row.col.f32.f16.f16.f32 "
        "{%0,%1,%2,%3}, {%4,%5,%6,%7}, {%8,%9}, {%0,%1,%2,%3};\n"
        : "+f"(c[0]), "+f"(c[1]), "+f"(c[2]), "+f"(c[3])
        : "r"(a0), "r"(a1), "r"(a2), "r"(a3), "r"(b0), "r"(b1));
}
__device__ __forceinline__ void ldm_x4(unsigned* r, unsigned addr) {
    asm volatile("ldmatrix.sync.aligned.m8n8.x4.shared.b16 {%0,%1,%2,%3}, [%4];"
                 : "=r"(r[0]), "=r"(r[1]), "=r"(r[2]), "=r"(r[3]) : "r"(addr));
}
__device__ __forceinline__ void ldm_x4t(unsigned* r, unsigned addr) {
    asm volatile("ldmatrix.sync.aligned.m8n8.x4.trans.shared.b16 {%0,%1,%2,%3}, [%4];"
                 : "=r"(r[0]), "=r"(r[1]), "=r"(r[2]), "=r"(r[3]) : "r"(addr));
}
__device__ __forceinline__ void cp16(void* s, const void* g) {
    unsigned sa = scvt(s);
    asm volatile("cp.async.ca.shared.global [%0], [%1], 16;" :: "r"(sa), "l"(g));
}

// ---------------- fused prep: weights->half (vectorized) + LN1 (one launch) ----------
// weight part: 1152 blocks x 128 thr x 8 elems; LN part: 16384 blocks (one row each).
__global__ void prep_k(const float* __restrict__ q, const float* __restrict__ k,
                       const float* __restrict__ v, const float* __restrict__ o,
                       const float* __restrict__ w1, const float* __restrict__ w2,
                       __half* __restrict__ wh,
                       const float* __restrict__ X, const float* __restrict__ ln1w,
                       const float* __restrict__ ln1b, __half* __restrict__ t_h) {
    int bid = blockIdx.x;
    __shared__ float red[4], red2[4];
    if (bid < 1152) {
        int i8 = (bid * 128 + threadIdx.x) * 8;
        const float* src; int off;
        if (i8 < 147456)      { src = q;  off = i8; }
        else if (i8 < 294912) { src = k;  off = i8 - 147456; }
        else if (i8 < 442368) { src = v;  off = i8 - 294912; }
        else if (i8 < 589824) { src = o;  off = i8 - 442368; }
        else if (i8 < 884736) { src = w1; off = i8 - 589824; }
        else                  { src = w2; off = i8 - 884736; }
        float4 a = *(const float4*)(src + off);
        float4 b2 = *(const float4*)(src + off + 4);
        __half2 h0 = __floats2half2_rn(a.x, a.y);
        __half2 h1 = __floats2half2_rn(a.z, a.w);
        __half2 h2 = __floats2half2_rn(b2.x, b2.y);
        __half2 h3 = __floats2half2_rn(b2.z, b2.w);
        uint4 pk;
        pk.x = *reinterpret_cast<unsigned*>(&h0);
        pk.y = *reinterpret_cast<unsigned*>(&h1);
        pk.z = *reinterpret_cast<unsigned*>(&h2);
        pk.w = *reinterpret_cast<unsigned*>(&h3);
        *(uint4*)(wh + i8) = pk;
        return;
    }
    int row = bid - 1152;
    const float* xr = X + (size_t)row * D_;
    int tid = threadIdx.x;
    float v0 = xr[tid], v1 = xr[tid + 128], v2 = xr[tid + 256];
    float s = v0 + v1 + v2;
    #pragma unroll
    for (int oo = 16; oo > 0; oo >>= 1) s += __shfl_xor_sync(0xffffffffu, s, oo);
    if ((tid & 31) == 0) red[tid >> 5] = s;
    __syncthreads();
    float mu = (red[0] + red[1] + red[2] + red[3]) * (1.0f / D_);
    float d0 = v0 - mu, d1 = v1 - mu, d2 = v2 - mu;
    float sq = d0 * d0 + d1 * d1 + d2 * d2;
    #pragma unroll
    for (int oo = 16; oo > 0; oo >>= 1) sq += __shfl_xor_sync(0xffffffffu, sq, oo);
    if ((tid & 31) == 0) red2[tid >> 5] = sq;
    __syncthreads();
    float var = (red2[0] + red2[1] + red2[2] + red2[3]) * (1.0f / D_);
    float rstd = rsqrtf(var + 1e-5f);
    __half* oh = t_h + (size_t)row * D_;
    oh[tid]       = __float2half(d0 * rstd * ln1w[tid]       + ln1b[tid]);
    oh[tid + 128] = __float2half(d1 * rstd * ln1w[tid + 128] + ln1b[tid + 128]);
    oh[tid + 256] = __float2half(d2 * rstd * ln1w[tid + 256] + ln1b[tid + 256]);
}

// ---------------- LayerNorm (row D=384) -> half only ----------------
__global__ void ln_h(const float* __restrict__ x, const float* __restrict__ w,
                     const float* __restrict__ b, __half* __restrict__ outh) {
    int row = blockIdx.x;
    const float* xr = x + (size_t)row * D_;
    int tid = threadIdx.x;
    float v0 = xr[tid], v1 = xr[tid + 128], v2 = xr[tid + 256];
    float s = v0 + v1 + v2;
    __shared__ float red[4], red2[4];
    #pragma unroll
    for (int o = 16; o > 0; o >>= 1) s += __shfl_xor_sync(0xffffffffu, s, o);
    if ((tid & 31) == 0) red[tid >> 5] = s;
    __syncthreads();
    float mu = (red[0] + red[1] + red[2] + red[3]) * (1.0f / D_);
    float d0 = v0 - mu, d1 = v1 - mu, d2 = v2 - mu;
    float sq = d0 * d0 + d1 * d1 + d2 * d2;
    #pragma unroll
    for (int o = 16; o > 0; o >>= 1) sq += __shfl_xor_sync(0xffffffffu, sq, o);
    if ((tid & 31) == 0) red2[tid >> 5] = sq;
    __syncthreads();
    float var = (red2[0] + red2[1] + red2[2] + red2[3]) * (1.0f / D_);
    float rstd = rsqrtf(var + 1e-5f);
    __half* oh = outh + (size_t)row * D_;
    oh[tid]       = __float2half(d0 * rstd * w[tid]       + b[tid]);
    oh[tid + 128] = __float2half(d1 * rstd * w[tid + 128] + b[tid + 128]);
    oh[tid + 256] = __float2half(d2 * rstd * w[tid + 256] + b[tid + 256]);
}

// ======================= fp16 tensor-core GEMM, NT, 3-stage 1-sync (R12) ==============
// RESMODE: 0 = none, 1 = fp32 residual, 2 = half residual.
#define GST_H  10240                  // halves per stage (A 5120 + W 5120)
#define GST_B  20480                  // bytes per stage

template <int ACT, bool BIAS, int RESMODE, bool OUTH>
__global__ void __launch_bounds__(256) gemm_h(
    const __half* __restrict__ A,
    const __half* __restrict__ Wa, const __half* __restrict__ Wb2,
    const __half* __restrict__ Wc,
    const float* __restrict__ bias, const float* __restrict__ resf,
    const __half* __restrict__ resh,
    __half* __restrict__ Ch, float* __restrict__ Cf,
    int K, int ldc, int nseg, float alpha) {
    extern __shared__ __half gsm[];

    int tid = threadIdx.x, lane = tid & 31, wid = tid >> 5;
    int wm = wid & 1, wn = wid >> 1;
    int g = lane >> 2, t = lane & 3;
    int m0 = blockIdx.y * 128, n0g = blockIdx.x * 128;
    int seg = n0g / nseg;
    const __half* W = (seg == 0) ? Wa : ((seg == 1) ? Wb2 : Wc);
    int n0 = n0g - seg * nseg;
    float asc = (seg == 0) ? alpha : 1.0f;

    int r1 = tid >> 2, c1 = (tid & 3) * 8;      // row, col(halves)
    const __half* Ap = A + (size_t)(m0 + r1) * K + c1;
    const __half* Wp = W + (size_t)(n0 + r1) * K + c1;

    unsigned base = scvt(gsm);
    int arow = lane & 15, asel = (lane & 16) ? 8 : 0;
    int brow = (lane & 7) + ((lane & 16) ? 8 : 0), bsel = (lane & 8) ? 8 : 0;
    unsigned aOff = ((wm * 64 + arow) * 40 + asel) * 2;
    unsigned wOff = 10240 + ((wn * 32 + brow) * 40 + bsel) * 2;

    float acc[4][4][4] = {};
    int nk = K / 32;

    #pragma unroll
    for (int s = 0; s < 2; s++) {
        __half* dA = gsm + s * GST_H + r1 * 40 + c1;
        __half* dW = dA + 5120;
        cp16(dA, Ap + s * 32);           cp16(dA + 64 * 40, Ap + (size_t)64 * K + s * 32);
        cp16(dW, Wp + s * 32);           cp16(dW + 64 * 40, Wp + (size_t)64 * K + s * 32);
        asm volatile("cp.async.commit_group;");
    }

    for (int it = 0; it < nk; it++) {
        if (it + 1 < nk) asm volatile("cp.async.wait_group 1;");
        else             asm volatile("cp.async.wait_group 0;");
        __syncthreads();

        if (it + 2 < nk) {
            int st = (it + 2) % 3;
            int k0 = (it + 2) * 32;
            __half* dA = gsm + st * GST_H + r1 * 40 + c1;
            __half* dW = dA + 5120;
            cp16(dA, Ap + k0);           cp16(dA + 64 * 40, Ap + (size_t)64 * K + k0);
            cp16(dW, Wp + k0);           cp16(dW + 64 * 40, Wp + (size_t)64 * K + k0);
            asm volatile("cp.async.commit_group;");
        }

        unsigned stB = base + (unsigned)((it % 3) * GST_B);
        unsigned aBase = stB + aOff, wBase = stB + wOff;
        #pragma unroll
        for (int kc = 0; kc < 2; kc++) {
            unsigned a[4][4];
            #pragma unroll
            for (int mf = 0; mf < 4; mf++)
                ldm_x4(a[mf], aBase + mf * 16 * 80 + kc * 32);
            unsigned b[4][2];
            #pragma unroll
            for (int nfp = 0; nfp < 2; nfp++) {
                unsigned r[4];
                ldm_x4(r, wBase + nfp * 16 * 80 + kc * 32);
                b[2 * nfp][0] = r[0]; b[2 * nfp][1] = r[1];
                b[2 * nfp + 1][0] = r[2]; b[2 * nfp + 1][1] = r[3];
            }
            #pragma unroll
            for (int mf = 0; mf < 4; mf++)
                #pragma unroll
                for (int nf = 0; nf < 4; nf++)
                    mma_f16(acc[mf][nf], a[mf][0], a[mf][1], a[mf][2], a[mf][3],
                            b[nf][0], b[nf][1]);
        }
    }

    #pragma unroll
    for (int mf = 0; mf < 4; mf++) {
        int r0 = m0 + wm * 64 + mf * 16 + g;
        #pragma unroll
        for (int nf = 0; nf < 4; nf++) {
            int c = n0g + wn * 32 + nf * 8 + 2 * t;
            float v0 = acc[mf][nf][0] * asc, v1 = acc[mf][nf][1] * asc;
            float v2 = acc[mf][nf][2] * asc, v3 = acc[mf][nf][3] * asc;
            if (BIAS) {
                float b0v = bias[c], b1v = bias[c + 1];
                v0 += b0v; v1 += b1v; v2 += b0v; v3 += b1v;
            }
            if (ACT == 1) {
                v0 = gelu_exact(v0); v1 = gelu_exact(v1);
                v2 = gelu_exact(v2); v3 = gelu_exact(v3);
            }
            if (RESMODE == 1) {
                v0 += resf[(size_t)r0 * ldc + c];
                v1 += resf[(size_t)r0 * ldc + c + 1];
                v2 += resf[(size_t)(r0 + 8) * ldc + c];
                v3 += resf[(size_t)(r0 + 8) * ldc + c + 1];
            } else if (RESMODE == 2) {
                __half2 ra = *(const __half2*)(resh + (size_t)r0 * ldc + c);
                __half2 rb = *(const __half2*)(resh + (size_t)(r0 + 8) * ldc + c);
                v0 += __half2float(ra.x); v1 += __half2float(ra.y);
                v2 += __half2float(rb.x); v3 += __half2float(rb.y);
            }
            if (OUTH) {
                *(__half2*)(Ch + (size_t)r0 * ldc + c)       = __floats2half2_rn(v0, v1);
                *(__half2*)(Ch + (size_t)(r0 + 8) * ldc + c) = __floats2half2_rn(v2, v3);
            } else {
                *(float2*)(Cf + (size_t)r0 * ldc + c)       = make_float2(v0, v1);
                *(float2*)(Cf + (size_t)(r0 + 8) * ldc + c) = make_float2(v2, v3);
            }
        }
    }
}

// ======================= fp16 flash attention (R12 version — best) =======================
#define FQ_STR 72
#define FT 64
#define FKV (FT * FQ_STR)        // 4608 halves per buffer

__global__ void __launch_bounds__(128) flash_h(const __half* __restrict__ qkv,
                                               __half* __restrict__ o_out) {
    extern __shared__ __half fsm[];
    __half* sQ = fsm;                      // 128*72
    __half* sK = fsm + 128 * FQ_STR;       // 2 * FKV
    __half* sV = sK + 2 * FKV;             // 2 * FKV

    int tid = threadIdx.x, lane = tid & 31, wid = tid >> 5;
    int g = lane >> 2, t = lane & 3;
    int bh = blockIdx.y, b = bh / H_, h = bh % H_;
    int q0 = blockIdx.x * 128;
    const __half* qb = qkv + (size_t)b * N_ * 1152 + h * 64;
    const __half* kb = qb + 384;
    const __half* vb = qb + 768;

    #pragma unroll
    for (int i = 0; i < 8; i++) {
        int id = tid + i * 128, row = id >> 3, cg = (id & 7) * 8;
        cp16(&sQ[row * FQ_STR + cg], qb + (size_t)(q0 + row) * 1152 + cg);
    }
    #pragma unroll
    for (int i = 0; i < 4; i++) {
        int id = tid + i * 128, row = id >> 3, cg = (id & 7) * 8;
        cp16(&sK[row * FQ_STR + cg], kb + (size_t)row * 1152 + cg);
        cp16(&sV[row * FQ_STR + cg], vb + (size_t)row * 1152 + cg);
    }
    asm volatile("cp.async.commit_group;");

    unsigned qB = scvt(sQ), kB = scvt(sK), vB = scvt(sV);
    int arow = lane & 15, asel = (lane & 16) ? 8 : 0;
    int brow = (lane & 7) + ((lane & 16) ? 8 : 0), bsel = (lane & 8) ? 8 : 0;
    unsigned kAddr0 = kB + (brow * FQ_STR + bsel) * 2;
    unsigned vAddr0 = vB + (arow * FQ_STR + asel) * 2;

    unsigned qf[2][4][4];
    float lacc[2][4] = {};
    float o[2][8][4] = {};

    for (int j = 0; j < 16; j++) {
        if (j < 15) {
            __half* dK = sK + ((j + 1) & 1) * FKV;
            __half* dV = sV + ((j + 1) & 1) * FKV;
            const __half* kg = kb + (size_t)(j + 1) * FT * 1152;
            const __half* vg = vb + (size_t)(j + 1) * FT * 1152;
            #pragma unroll
            for (int i = 0; i < 4; i++) {
                int id = tid + i * 128, row = id >> 3, cg = (id & 7) * 8;
                cp16(&dK[row * FQ_STR + cg], kg + (size_t)row * 1152 + cg);
                cp16(&dV[row * FQ_STR + cg], vg + (size_t)row * 1152 + cg);
            }
            asm volatile("cp.async.commit_group;");
            asm volatile("cp.async.wait_group 1;");
        } else {
            asm volatile("cp.async.wait_group 0;");
        }
        __syncthreads();

        if (j == 0) {
            #pragma unroll
            for (int grp = 0; grp < 2; grp++) {
                unsigned qAddr = qB + ((32 * wid + 16 * grp + arow) * FQ_STR + asel) * 2;
                #pragma unroll
                for (int kc = 0; kc < 4; kc++)
                    ldm_x4(qf[grp][kc], qAddr + kc * 32);
            }
        }

        unsigned kA = kAddr0 + (j & 1) * (FKV * 2);
        unsigned vA = vAddr0 + (j & 1) * (FKV * 2);

        // ---- S = Q' K^T (Q pre-scaled to log2 domain) ----
        float sc[2][8][4];
        #pragma unroll
        for (int grp = 0; grp < 2; grp++)
            #pragma unroll
            for (int nf = 0; nf < 8; nf++)
                sc[grp][nf][0] = sc[grp][nf][1] = sc[grp][nf][2] = sc[grp][nf][3] = 0.f;
        #pragma unroll
        for (int kc = 0; kc < 4; kc++) {
            #pragma unroll
            for (int nfp = 0; nfp < 4; nfp++) {
                unsigned bk[4];
                ldm_x4(bk, kA + nfp * 16 * (FQ_STR * 2) + kc * 32);
                #pragma unroll
                for (int grp = 0; grp < 2; grp++) {
                    mma_f16(sc[grp][2 * nfp],     qf[grp][kc][0], qf[grp][kc][1],
                            qf[grp][kc][2], qf[grp][kc][3], bk[0], bk[1]);
                    mma_f16(sc[grp][2 * nfp + 1], qf[grp][kc][0], qf[grp][kc][1],
                            qf[grp][kc][2], qf[grp][kc][3], bk[2], bk[3]);
                }
            }
        }

        // ---- P = 2^S via ex2.approx.f16x2 ----
        unsigned ph[2][8][2];
        #pragma unroll
        for (int grp = 0; grp < 2; grp++) {
            #pragma unroll
            for (int nf = 0; nf < 8; nf++) {
                ph[grp][nf][0] = ex2_h2(pack2(sc[grp][nf][0], sc[grp][nf][1]));
                ph[grp][nf][1] = ex2_h2(pack2(sc[grp][nf][2], sc[grp][nf][3]));
            }
        }

        // ---- l += P @ ones ----
        #pragma unroll
        for (int kc2 = 0; kc2 < 4; kc2++)
            #pragma unroll
            for (int grp = 0; grp < 2; grp++)
                mma_f16(lacc[grp], ph[grp][2 * kc2][0], ph[grp][2 * kc2][1],
                        ph[grp][2 * kc2 + 1][0], ph[grp][2 * kc2 + 1][1],
                        ONESH, ONESH);

        // ---- O += P V ----
        #pragma unroll
        for (int kc2 = 0; kc2 < 4; kc2++) {
            #pragma unroll
            for (int nfq = 0; nfq < 4; nfq++) {
                unsigned bv[4];
                ldm_x4t(bv, vA + kc2 * 16 * (FQ_STR * 2) + nfq * 32);
                #pragma unroll
                for (int grp = 0; grp < 2; grp++) {
                    unsigned a0 = ph[grp][2 * kc2][0], a1 = ph[grp][2 * kc2][1];
                    unsigned a2 = ph[grp][2 * kc2 + 1][0], a3 = ph[grp][2 * kc2 + 1][1];
                    mma_f16(o[grp][2 * nfq],     a0, a1, a2, a3, bv[0], bv[1]);
                    mma_f16(o[grp][2 * nfq + 1], a0, a1, a2, a3, bv[2], bv[3]);
                }
            }
        }
        __syncthreads();
    }

    // ---- epilogue: l already reduced by the ones-MMA ----
    #pragma unroll
    for (int grp = 0; grp < 2; grp++) {
        float i0 = 1.0f / lacc[grp][0], i1 = 1.0f / lacc[grp][2];
        size_t tok0 = (size_t)(b * N_ + q0 + 32 * wid + 16 * grp + g);
        __half* out0 = o_out + tok0 * D_ + h * 64;
        __half* out1 = out0 + (size_t)8 * D_;
        #pragma unroll
        for (int nf2 = 0; nf2 < 8; nf2++) {
            int c = nf2 * 8 + 2 * t;
            *(__half2*)(out0 + c) = __floats2half2_rn(o[grp][nf2][0] * i0, o[grp][nf2][1] * i0);
            *(__half2*)(out1 + c) = __floats2half2_rn(o[grp][nf2][2] * i1, o[grp][nf2][3] * i1);
        }
    }
}

// ---------------- launch ----------------
extern "C" void kernel_launch(void* const* d_in, const int* in_sizes, int n_in,
                              void* d_out, int out_size) {
    const float* X    = (const float*)d_in[0];
    const float* Wq   = (const float*)d_in[1];
    const float* Wk   = (const float*)d_in[2];
    const float* Wv   = (const float*)d_in[3];
    const float* Wo   = (const float*)d_in[4];
    const float* bo   = (const float*)d_in[5];
    const float* ln1w = (const float*)d_in[6];
    const float* ln1b = (const float*)d_in[7];
    const float* ln2w = (const float*)d_in[8];
    const float* ln2b = (const float*)d_in[9];
    const float* W1   = (const float*)d_in[10];
    const float* b1   = (const float*)d_in[11];
    const float* W2   = (const float*)d_in[12];
    const float* b2   = (const float*)d_in[13];
    float* out = (float*)d_out;

    __half *wh, *t_h, *qkv_h, *o_h, *x2_h, *h_h;
    float *y;
    cudaGetSymbolAddress((void**)&wh,    g_wh);
    cudaGetSymbolAddress((void**)&t_h,   g_t_h);
    cudaGetSymbolAddress((void**)&qkv_h, g_qkv_h);
    cudaGetSymbolAddress((void**)&o_h,   g_o_h);
    cudaGetSymbolAddress((void**)&x2_h,  g_x2_h);
    cudaGetSymbolAddress((void**)&h_h,   g_h_h);
    cudaGetSymbolAddress((void**)&y,     g_y);

    const int gsmem = 3 * GST_B;                        // 61440 B
    const int fa_smem = (128 * FQ_STR + 4 * FKV) * 2;   // 55296 B
    cudaFuncSetAttribute(flash_h, cudaFuncAttributeMaxDynamicSharedMemorySize, fa_smem);
    cudaFuncSetAttribute(gemm_h<0, false, 0, true>,
                         cudaFuncAttributeMaxDynamicSharedMemorySize, gsmem);
    cudaFuncSetAttribute(gemm_h<0, true, 1, false>,
                         cudaFuncAttributeMaxDynamicSharedMemorySize, gsmem);
    cudaFuncSetAttribute(gemm_h<1, true, 0, true>,
                         cudaFuncAttributeMaxDynamicSharedMemorySize, gsmem);
    cudaFuncSetAttribute(gemm_h<0, true, 2, false>,
                         cudaFuncAttributeMaxDynamicSharedMemorySize, gsmem);

    const float qscale = 0.125f * 1.4426950408889634f;   // 1/sqrt(64) * log2(e)

    // 0) weights->half (vectorized) + LN1 (single launch)
    prep_k<<<1152 + MTOK, 128>>>(Wq, Wk, Wv, Wo, W1, W2, wh, X, ln1w, ln1b, t_h);

    // 1) fused QKV projection; Q segment pre-scaled to log2 domain
    {
        dim3 gsz(9, 128);
        gemm_h<0, false, 0, true><<<gsz, 256, gsmem>>>(t_h,
            wh + WOFF_Q, wh + WOFF_K, wh + WOFF_V,
            nullptr, nullptr, nullptr, qkv_h, nullptr, D_, 3 * D_, 384, qscale);
    }

    // 2) flash attention -> o_h
    {
        dim3 gsz(8, B_ * H_);
        flash_h<<<gsz, 128, fa_smem>>>(qkv_h, o_h);
    }

    // 3) y = X + (o @ Wo^T + bo)   (fp32 out, fp32 residual)
    {
        dim3 gsz(3, 128);
        gemm_h<0, true, 1, false><<<gsz, 256, gsmem>>>(o_h,
            wh + WOFF_O, wh + WOFF_O, wh + WOFF_O,
            bo, X, nullptr, nullptr, y, D_, D_, 1 << 30, 1.0f);
    }

    // 4) LN2 -> half only
    ln_h<<<MTOK, 128>>>(y, ln2w, ln2b, x2_h);

    // 5) h = gelu(x2 @ W1^T + b1) -> half
    {
        dim3 gsz(6, 128);
        gemm_h<1, true, 0, true><<<gsz, 256, gsmem>>>(x2_h,
            wh + WOFF_1, wh + WOFF_1, wh + WOFF_1,
            b1, nullptr, nullptr, h_h, nullptr, D_, 2 * D_, 1 << 30, 1.0f);
    }

    // 6) out = x2_h + (h @ W2^T + b2)   (fp32 out, HALF residual)
    {
        dim3 gsz(3, 128);
        gemm_h<0, true, 2, false><<<gsz, 256, gsmem>>>(h_h,
            wh + WOFF_2, wh + WOFF_2, wh + WOFF_2,
            b2, nullptr, x2_h, nullptr, out, 2 * D_, D_, 1 << 30, 1.0f);
    }
}